// round 9
// baseline (speedup 1.0000x reference)
#include <cuda_runtime.h>
#include <cuda_bf16.h>
#include <math.h>
#include <stdint.h>

#define Bx    256
#define OBSx  256
#define DINx  512
#define Dx    1024
#define Mx    32
#define HIDx  16
#define NSYx  64
#define ITERSx 4
#define SYNCHx 2080
#define DMx   (Dx * Mx)
#define BDx   (Bx * Dx)          // 262144
#define BDMx  (Bx * Dx * Mx)     // 8388608
#define NBLK  148

// ---------------- scratch (static device globals) ----------------
__device__ float g_y[2 * Bx * 2 * Dx];               // 2 K-split partials
__device__ __align__(16) float g_w1t[Dx * 1024];
__device__ float g_w2t[Dx * 32];
__device__ float g_decay[Mx * SYNCHx];
__device__ float g_invden[SYNCHx];
__device__ int   g_tri_i[SYNCHx];
__device__ int   g_tri_j[SYNCHx];
__device__ int   g_dones[Bx];
__device__ unsigned g_gbar;
__device__ __align__(16) float g_hst[ITERSx][BDx];   // [i][b*1024+d]
__device__ __align__(16) float g_hat[ITERSx][BDx];   // [i][d*256+b]

__device__ __align__(256) __nv_bfloat16 g_obshi[Bx * OBSx];
__device__ __align__(256) __nv_bfloat16 g_obslo[Bx * OBSx];
__device__ __align__(256) __nv_bfloat16 g_prehi[Bx * (DINx + Dx)];
__device__ __align__(256) __nv_bfloat16 g_prelo[Bx * (DINx + Dx)];
__device__ __align__(256) __nv_bfloat16 g_h1hi[Bx * Dx];
__device__ __align__(256) __nv_bfloat16 g_h1lo[Bx * Dx];
__device__ __align__(256) __nv_bfloat16 g_wb1hi[1024 * 256];
__device__ __align__(256) __nv_bfloat16 g_wb1lo[1024 * 256];
__device__ __align__(256) __nv_bfloat16 g_wb2hi[1024 * 512];
__device__ __align__(256) __nv_bfloat16 g_wb2lo[1024 * 512];
__device__ __align__(256) __nv_bfloat16 g_ws1hi[2048 * 1536];
__device__ __align__(256) __nv_bfloat16 g_ws1lo[2048 * 1536];
__device__ __align__(256) __nv_bfloat16 g_ws2hi[2048 * 1024];
__device__ __align__(256) __nv_bfloat16 g_ws2lo[2048 * 1024];

__device__ __forceinline__ float sigf(float x) {
    return __fdividef(1.0f, 1.0f + __expf(-x));
}
__device__ __forceinline__ void split2(float v, __nv_bfloat16* h, __nv_bfloat16* l) {
    __nv_bfloat16 hh = __float2bfloat16(v);
    *h = hh;
    *l = __float2bfloat16(v - __bfloat162float(hh));
}

// ================= PTX helpers =================
__device__ __forceinline__ uint32_t smem_u32(const void* p) {
    uint32_t a;
    asm("{ .reg .u64 t; cvta.to.shared.u64 t, %1; cvt.u32.u64 %0, t; }" : "=r"(a) : "l"(p));
    return a;
}
#define SW128(off) ((off) ^ (((off) >> 3) & 0x70))
#define CP_ASYNC16(dst, src) \
    asm volatile("cp.async.cg.shared.global [%0], [%1], 16;" :: "r"(dst), "l"(src))
#define CP_COMMIT()  asm volatile("cp.async.commit_group;" ::: "memory")
#define CP_WAIT(n)   asm volatile("cp.async.wait_group %0;" :: "n"(n) : "memory")
#define LDSM4(r, addr) \
    asm volatile("ldmatrix.sync.aligned.m8n8.x4.shared.b16 {%0,%1,%2,%3}, [%4];" \
        : "=r"((r)[0]), "=r"((r)[1]), "=r"((r)[2]), "=r"((r)[3]) : "r"(addr))
#define MMA16816(acc, a, b0, b1) \
    asm volatile("mma.sync.aligned.m16n8k16.row.col.f32.bf16.bf16.f32 " \
        "{%0,%1,%2,%3}, {%4,%5,%6,%7}, {%8,%9}, {%0,%1,%2,%3};" \
        : "+f"((acc)[0]), "+f"((acc)[1]), "+f"((acc)[2]), "+f"((acc)[3]) \
        : "r"((a)[0]), "r"((a)[1]), "r"((a)[2]), "r"((a)[3]), "r"(b0), "r"(b1))

// ================= grid barrier (all CTAs co-resident) =================
__device__ __forceinline__ void gsync(unsigned& target) {
    __threadfence();
    __syncthreads();
    target += gridDim.x;
    if (threadIdx.x == 0) {
        atomicAdd(&g_gbar, 1u);
        while (*((volatile unsigned*)&g_gbar) < target) __nanosleep(32);
    }
    __syncthreads();
    __threadfence();
}

// ================= GEMM core (device) =================
#define GBUF_BYTES 32768
#define GSTAGES 3
__device__ void gemm_unit(
    const __nv_bfloat16* __restrict__ Ahi, const __nv_bfloat16* __restrict__ Alo,
    const __nv_bfloat16* __restrict__ Bhi, const __nv_bfloat16* __restrict__ Blo,
    float* __restrict__ Cz, int row0, int col0, int koff, int NC,
    int lda, int ldb, int N, uint32_t abase)
{
    int tid = threadIdx.x;
    int lane = tid & 31;
    int wid = tid >> 5;
    int warp_m = wid & 1;
    int warp_n = wid >> 1;

    float acc[2][2][4];
#pragma unroll
    for (int i = 0; i < 2; i++)
#pragma unroll
        for (int j = 0; j < 2; j++)
#pragma unroll
            for (int q = 0; q < 4; q++) acc[i][j][q] = 0.0f;

    auto load_chunk = [&](int buf, int k0) {
        uint32_t bb = abase + buf * GBUF_BYTES;
#pragma unroll
        for (int i = 0; i < 2; i++) {
            int u = tid + i * 256;
            int r = u >> 3, ch = u & 7;
            uint32_t soff = SW128((uint32_t)(r * 128 + ch * 16));
            size_t goA = (size_t)(row0 + r) * lda + koff + k0 + ch * 8;
            size_t goB = (size_t)(col0 + r) * ldb + koff + k0 + ch * 8;
            CP_ASYNC16(bb + soff,          Ahi + goA);
            CP_ASYNC16(bb + 8192 + soff,   Alo + goA);
            CP_ASYNC16(bb + 16384 + soff,  Bhi + goB);
            CP_ASYNC16(bb + 24576 + soff,  Blo + goB);
        }
    };

    load_chunk(0, 0);
    CP_COMMIT();
    load_chunk(1, 64);
    CP_COMMIT();

    int a_r = warp_m * 32 + (lane & 15);
    int a_csel = (lane >> 4) << 3;
    int b_r = warp_n * 16 + (lane & 7) + ((lane >> 4) << 3);
    int b_csel = ((lane >> 3) & 1) << 3;

    int buf = 0, pbuf = 2;
    for (int c = 0; c < NC; c++) {
        CP_WAIT(GSTAGES - 2);
        __syncthreads();
        if (c + 2 < NC) load_chunk(pbuf, (c + 2) * 64);
        CP_COMMIT();

        uint32_t bb = abase + buf * GBUF_BYTES;
#pragma unroll
        for (int kk = 0; kk < 4; kk++) {
            int k0 = kk * 16;
            uint32_t ah[2][4], al[2][4], bh[4], bl[4];
#pragma unroll
            for (int mf = 0; mf < 2; mf++) {
                uint32_t off = SW128((uint32_t)((a_r + mf * 16) * 128 + (k0 + a_csel) * 2));
                LDSM4(ah[mf], bb + off);
                LDSM4(al[mf], bb + 8192 + off);
            }
            {
                uint32_t off = SW128((uint32_t)(b_r * 128 + (k0 + b_csel) * 2));
                LDSM4(bh, bb + 16384 + off);
                LDSM4(bl, bb + 24576 + off);
            }
#pragma unroll
            for (int mf = 0; mf < 2; mf++) {
#pragma unroll
                for (int nf = 0; nf < 2; nf++) {
                    MMA16816(acc[mf][nf], ah[mf], bh[2 * nf], bh[2 * nf + 1]);
                    MMA16816(acc[mf][nf], ah[mf], bl[2 * nf], bl[2 * nf + 1]);
                    MMA16816(acc[mf][nf], al[mf], bh[2 * nf], bh[2 * nf + 1]);
                }
            }
        }
        buf = (buf == GSTAGES - 1) ? 0 : buf + 1;
        pbuf = (pbuf == GSTAGES - 1) ? 0 : pbuf + 1;
    }

    int gid = lane >> 2, tig = lane & 3;
#pragma unroll
    for (int mf = 0; mf < 2; mf++) {
#pragma unroll
        for (int nf = 0; nf < 2; nf++) {
            int r = row0 + warp_m * 32 + mf * 16 + gid;
            int cc = col0 + warp_n * 16 + nf * 8 + tig * 2;
            float2 o0 = { acc[mf][nf][0], acc[mf][nf][1] };
            float2 o1 = { acc[mf][nf][2], acc[mf][nf][3] };
            *(float2*)&Cz[(size_t)r * N + cc] = o0;
            *(float2*)&Cz[(size_t)(r + 8) * N + cc] = o1;
        }
    }
    __syncthreads();   // smem buffers safe for next unit
}

// standalone GEMM kernel (backbone only)
__global__ void __launch_bounds__(256) k_tgemm(
    const __nv_bfloat16* __restrict__ Ahi, const __nv_bfloat16* __restrict__ Alo,
    const __nv_bfloat16* __restrict__ Bhi, const __nv_bfloat16* __restrict__ Blo,
    float* __restrict__ C, int Kloc, int lda, int ldb, int N)
{
    extern __shared__ char smem_raw[];
    uint32_t sbase = smem_u32(smem_raw);
    uint32_t abase = (sbase + 1023u) & ~1023u;
    gemm_unit(Ahi, Alo, Bhi, Blo, C + (size_t)blockIdx.z * Bx * N,
              blockIdx.y * 64, blockIdx.x * 64, blockIdx.z * Kloc, Kloc >> 6,
              lda, ldb, N, abase);
}

// ================= prep kernels =================
__device__ void tsplit_block(const float* __restrict__ W, int K, int N,
                             __nv_bfloat16* __restrict__ Ohi, __nv_bfloat16* __restrict__ Olo,
                             int local) {
    __shared__ float t[32][33];
    int ktiles = K >> 5;
    int kt = local % ktiles, nt = local / ktiles;
    int k0 = kt * 32, n0 = nt * 32;
    int tx = threadIdx.x & 31, ty = threadIdx.x >> 5;
    for (int i = ty; i < 32; i += 8)
        t[i][tx] = W[(size_t)(k0 + i) * N + n0 + tx];
    __syncthreads();
    for (int i = ty; i < 32; i += 8) {
        float v = t[tx][i];
        size_t o = (size_t)(n0 + i) * K + k0 + tx;
        __nv_bfloat16 h, l;
        split2(v, &h, &l);
        Ohi[o] = h; Olo[o] = l;
    }
}

__global__ void __launch_bounds__(256) k_prep_main(
    const unsigned char* __restrict__ dones_raw,
    const float* __restrict__ dp,
    const float* __restrict__ obs,
    const float* __restrict__ bw1, const float* __restrict__ bw2) {
    int bid = blockIdx.x, tid = threadIdx.x;
    if (bid == 0) {
        __shared__ int mode;
        if (tid == 0) {
            bool nzoff = false, floatlike = true, anynz = false;
            for (int i = 0; i < Bx; i++) {
                unsigned char v = dones_raw[i];
                if (v) {
                    anynz = true;
                    int r = i & 3;
                    if (r != 0) nzoff = true;
                    bool okf = (r == 2 && v == 0x80) || (r == 3 && v == 0x3F);
                    if (!okf) floatlike = false;
                }
            }
            mode = (nzoff && floatlike && anynz) ? 2 : (nzoff ? 0 : 1);
        }
        __syncthreads();
        int b = tid, m = mode, v;
        if (m == 0)      v = (dones_raw[b] != 0);
        else if (m == 1) v = (((const int*)dones_raw)[b] != 0);
        else             v = (((const float*)dones_raw)[b] != 0.0f);
        g_dones[b] = v;
    } else if (bid < 10) {
        int s = (bid - 1) * 256 + tid;
        if (s < SYNCHx) {
            float c = fminf(fmaxf(dp[s], 0.0f), 4.0f);
            float sum = 0.0f;
            for (int m = 0; m < Mx; m++) {
                float v = __expf(-(float)(Mx - 1 - m) * c);
                g_decay[m * SYNCHx + s] = v;
                sum += v;
            }
            g_invden[s] = rsqrtf(sum);
            int i = 0, base = 0;
            while (s >= base + (NSYx - i)) { base += NSYx - i; i++; }
            g_tri_i[s] = i;
            g_tri_j[s] = i + (s - base);
        }
    } else if (bid < 266) {
        int i = (bid - 10) * 256 + tid;
        split2(obs[i], &g_obshi[i], &g_obslo[i]);
    } else if (bid < 522) {
        tsplit_block(bw1, 256, 1024, g_wb1hi, g_wb1lo, bid - 266);
    } else {
        tsplit_block(bw2, 512, 1024, g_wb2hi, g_wb2lo, bid - 522);
    }
}

__global__ void __launch_bounds__(256) k_prep_side(
    const float* __restrict__ nw1, const float* __restrict__ nw2,
    const float* __restrict__ sw1, const float* __restrict__ sw2) {
    int bid = blockIdx.x, tid = threadIdx.x;
    if (bid < 4096) {
        int idx = bid * 256 + tid;
        int d = idx >> 10, mh = idx & 1023;
        g_w1t[idx] = nw1[mh * Dx + d];
        if (idx < Dx * 32) {
            int d2 = idx >> 5, hc = idx & 31;
            g_w2t[idx] = nw2[hc * Dx + d2];
        }
    } else if (bid < 7168) {
        tsplit_block(sw1, 1536, 2048, g_ws1hi, g_ws1lo, bid - 4096);
    } else {
        tsplit_block(sw2, 1024, 2048, g_ws2hi, g_ws2lo, bid - 7168);
    }
}

// ====== standalone GLU+LN (backbone; blockDim == halfN) ======
__global__ void __launch_bounds__(1024) k_gluln_split(
    const float* __restrict__ y, int halfN, int KS,
    const float* __restrict__ bias,
    const float* __restrict__ sc, const float* __restrict__ bi,
    __nv_bfloat16* __restrict__ ohi, __nv_bfloat16* __restrict__ olo,
    int ostride, int gather,
    const float* __restrict__ at_in,
    const float* __restrict__ start_at) {
    __shared__ float red_s[32], red_q[32];
    int row = blockIdx.x, tid = threadIdx.x;
    int nw = blockDim.x >> 5;
    size_t rstride = (size_t)Bx * 2 * halfN;
    const float* yr = y + (size_t)row * 2 * halfN;
    int c = tid;
    float a = bias[c];
    float g = bias[halfN + c];
    for (int z = 0; z < KS; z++) {
        a += yr[z * rstride + c];
        g += yr[z * rstride + halfN + c];
    }
    float val = a * sigf(g);
    float sum = val, sq = val * val;
#pragma unroll
    for (int o = 16; o > 0; o >>= 1) {
        sum += __shfl_xor_sync(0xffffffffu, sum, o);
        sq  += __shfl_xor_sync(0xffffffffu, sq, o);
    }
    int w = tid >> 5;
    if ((tid & 31) == 0) { red_s[w] = sum; red_q[w] = sq; }
    __syncthreads();
    if (tid == 0) {
        float ts = 0.0f, tq = 0.0f;
        for (int i = 0; i < nw; i++) { ts += red_s[i]; tq += red_q[i]; }
        red_s[0] = ts; red_q[0] = tq;
    }
    __syncthreads();
    float invN = 1.0f / (float)halfN;
    float mean = red_s[0] * invN;
    float var = red_q[0] * invN - mean * mean;
    float inv = rsqrtf(var + 1e-6f);
    {
        float o_ = (val - mean) * inv * sc[c] + bi[c];
        size_t o = (size_t)row * ostride + c;
        split2(o_, &ohi[o], &olo[o]);
    }
    if (gather) {
        bool done = g_dones[row] != 0;
        for (int cc = tid; cc < Dx; cc += blockDim.x) {
            float v2 = done ? start_at[cc * 32 + 31]
                            : at_in[((size_t)(row * Dx + cc)) * 32 + 31];
            size_t o = (size_t)row * ostride + halfN + cc;
            split2(v2, &ohi[o], &olo[o]);
        }
    }
}

// ================= mega: per-phase device functions =================
// GLU+LN over 1024 cols, KS=2 partials; 256 threads, 4 cols/thread.
// mode 0: write bf16 hi/lo (stride 1024); mode 1: write fp32 to outf
__device__ void phase_gluln(const float* __restrict__ bias,
                            const float* __restrict__ sc, const float* __restrict__ bi,
                            __nv_bfloat16* __restrict__ ohi, __nv_bfloat16* __restrict__ olo,
                            float* __restrict__ outf, int mode, char* smem) {
    float* red_s = (float*)smem;
    float* red_q = (float*)smem + 8;
    int tid = threadIdx.x;
    const size_t rstride = (size_t)Bx * 2048;
    for (int r = blockIdx.x; r < Bx; r += (int)gridDim.x) {
        const float* yr = g_y + (size_t)r * 2048;
        float vv[4], sum = 0.0f, sq = 0.0f;
#pragma unroll
        for (int q = 0; q < 4; q++) {
            int c = tid + q * 256;
            float a = bias[c] + yr[c] + yr[rstride + c];
            float g = bias[1024 + c] + yr[1024 + c] + yr[rstride + 1024 + c];
            float val = a * sigf(g);
            vv[q] = val;
            sum += val;
            sq += val * val;
        }
#pragma unroll
        for (int o = 16; o > 0; o >>= 1) {
            sum += __shfl_xor_sync(0xffffffffu, sum, o);
            sq  += __shfl_xor_sync(0xffffffffu, sq, o);
        }
        int w = tid >> 5;
        if ((tid & 31) == 0) { red_s[w] = sum; red_q[w] = sq; }
        __syncthreads();
        if (tid == 0) {
            float ts = 0.0f, tq = 0.0f;
            for (int i = 0; i < 8; i++) { ts += red_s[i]; tq += red_q[i]; }
            red_s[0] = ts; red_q[0] = tq;
        }
        __syncthreads();
        float mean = red_s[0] * (1.0f / 1024.0f);
        float var = red_q[0] * (1.0f / 1024.0f) - mean * mean;
        float inv = rsqrtf(var + 1e-6f);
        __syncthreads();
#pragma unroll
        for (int q = 0; q < 4; q++) {
            int c = tid + q * 256;
            float o_ = (vv[q] - mean) * inv * sc[c] + bi[c];
            if (mode == 0) {
                size_t o = (size_t)r * 1024 + c;
                split2(o_, &ohi[o], &olo[o]);
            } else {
                outf[(size_t)r * 1024 + c] = o_;
            }
        }
    }
}

// NLM body (compile-time IT), one virtual block = blockIdx.x (<128)
template<int IT>
__device__ __noinline__ void nlm_body(
    const float* __restrict__ st_in, const float* __restrict__ start_st,
    const float* __restrict__ b1, const float* __restrict__ T1,
    const float* __restrict__ b2, const float* __restrict__ T2, char* smem) {
    float4* w1v = (float4*)smem;                    // 8*256 float4 = 32768B
    float* w2s  = (float*)(smem + 32768);           // 256 floats
    float* b1s  = (float*)(smem + 33792);           // 256 floats
    float* b2s  = (float*)(smem + 34816);           // 16 floats
    float* hsm  = (float*)(smem + 34880);           // 4*32*9 floats = 4608B
    float* xsm  = (float*)(smem + 39488);           // 32*9 floats
    float* invT = (float*)(smem + 40640);           // 2 floats
    int tid = threadIdx.x;
    int w = tid >> 5, lane = tid & 31;
    int d0 = blockIdx.x * 8;
    for (int u = tid; u < 2048; u += 256) {
        int dl = u >> 8, q = u & 255;
        w1v[dl * 256 + q] = ((const float4*)g_w1t)[(size_t)(d0 + dl) * 256 + q];
    }
    w2s[w * 32 + lane] = g_w2t[(d0 + w) * 32 + lane];
    b1s[w * 32 + lane] = b1[(d0 + w) * 32 + lane];
    if (tid < 16) b2s[tid] = b2[d0 * 2 + tid];
    if (tid == 0) { invT[0] = 1.0f / T1[0]; invT[1] = 1.0f / T2[0]; }
    __syncthreads();
    float iT1 = invT[0], iT2 = invT[1];
    int d = d0 + w;

    for (int ch = 0; ch < 8; ch++) {
        if (tid < (IT + 1) * 64) {
            int j = tid >> 6, rem = tid & 63, bl = rem >> 1, hf = rem & 1;
            float4 hv = *(const float4*)&g_hst[j][(size_t)(ch * 32 + bl) * Dx + d0 + hf * 4];
            hsm[j * 288 + bl * 9 + hf * 4 + 0] = hv.x;
            hsm[j * 288 + bl * 9 + hf * 4 + 1] = hv.y;
            hsm[j * 288 + bl * 9 + hf * 4 + 2] = hv.z;
            hsm[j * 288 + bl * 9 + hf * 4 + 3] = hv.w;
        }
        __syncthreads();
        int b = ch * 32 + lane;
        const float* stp = g_dones[b] ? (start_st + d * 32)
                                      : (st_in + ((size_t)(b << 10) + d) * 32);
        float sin[32];
#pragma unroll
        for (int q = 0; q < 8; q++) {
            float4 t4 = ((const float4*)stp)[q];
            sin[q * 4 + 0] = t4.x; sin[q * 4 + 1] = t4.y;
            sin[q * 4 + 2] = t4.z; sin[q * 4 + 3] = t4.w;
        }
        float hreg[IT + 1];
#pragma unroll
        for (int j = 0; j <= IT; j++) hreg[j] = hsm[j * 288 + lane * 9 + w];

        float x[32];
#pragma unroll
        for (int h = 0; h < 32; h++) x[h] = b1s[w * 32 + h];
#pragma unroll
        for (int m = 0; m < 32; m++) {
            float a = (m < 31 - IT) ? sin[m + IT + 1] : hreg[m - (31 - IT)];
#pragma unroll
            for (int q = 0; q < 8; q++) {
                float4 wv = w1v[w * 256 + m * 8 + q];
                x[q * 4 + 0] += a * wv.x;
                x[q * 4 + 1] += a * wv.y;
                x[q * 4 + 2] += a * wv.z;
                x[q * 4 + 3] += a * wv.w;
            }
        }
        float y0 = b2s[w * 2 + 0], y1 = b2s[w * 2 + 1];
#pragma unroll
        for (int h = 0; h < 16; h++) {
            float u = (x[h] * iT1) * sigf(x[h + 16] * iT1);
            y0 += u * w2s[w * 32 + h * 2 + 0];
            y1 += u * w2s[w * 32 + h * 2 + 1];
        }
        float r = (y0 * iT2) * sigf(y1 * iT2);
        g_hat[IT][(size_t)d * Bx + b] = r;
        if (IT < 3) {
            xsm[lane * 9 + w] = r;
            __syncthreads();
            int bl = tid >> 3, dl = tid & 7;
            float vv = xsm[bl * 9 + dl];
            __nv_bfloat16 hh, ll;
            split2(vv, &hh, &ll);
            size_t o = (size_t)(ch * 32 + bl) * (DINx + Dx) + DINx + d0 + dl;
            g_prehi[o] = hh; g_prelo[o] = ll;
        }
        __syncthreads();
    }
}

// final assembly + synchrony, virtual blocks over 1280
__device__ void phase_fin(float* __restrict__ out,
                          const float* __restrict__ st_in, const float* __restrict__ at_in,
                          const float* __restrict__ start_st, const float* __restrict__ start_at,
                          char* smem) {
    int tid = threadIdx.x;
    for (int vb = blockIdx.x; vb < 1024 + Bx; vb += (int)gridDim.x) {
        if (vb < 1024) {
            float* hsm = (float*)smem;    // 4*32*9 floats
            int dt = vb & 127, bt = vb >> 7;
            int d0 = dt * 8, b0 = bt * 32;
            {
                int j = tid >> 6, rem = tid & 63, bl = rem >> 1, hf = rem & 1;
                float4 hv = *(const float4*)&g_hst[j][(size_t)(b0 + bl) * Dx + d0 + hf * 4];
                hsm[j * 288 + bl * 9 + hf * 4 + 0] = hv.x;
                hsm[j * 288 + bl * 9 + hf * 4 + 1] = hv.y;
                hsm[j * 288 + bl * 9 + hf * 4 + 2] = hv.z;
                hsm[j * 288 + bl * 9 + hf * 4 + 3] = hv.w;
            }
            __syncthreads();
            int w = tid >> 5, lane = tid & 31;
            int d = d0 + w, b = b0 + lane;
            bool done = g_dones[b] != 0;
            const float* stp = done ? (start_st + d * 32) : (st_in + ((size_t)(b << 10) + d) * 32);
            const float* atp = done ? (start_at + d * 32) : (at_in + ((size_t)(b << 10) + d) * 32);
            float so[32], ao[32];
#pragma unroll
            for (int q = 1; q < 8; q++) {
                float4 t4 = ((const float4*)stp)[q];
                so[q * 4 - 4] = t4.x; so[q * 4 - 3] = t4.y; so[q * 4 - 2] = t4.z; so[q * 4 - 1] = t4.w;
                float4 u4 = ((const float4*)atp)[q];
                ao[q * 4 - 4] = u4.x; ao[q * 4 - 3] = u4.y; ao[q * 4 - 2] = u4.z; ao[q * 4 - 1] = u4.w;
            }
#pragma unroll
            for (int j = 0; j < 4; j++) {
                so[28 + j] = hsm[j * 288 + lane * 9 + w];
                ao[28 + j] = g_hat[j][(size_t)d * Bx + b];
            }
            float* o1 = out + ((size_t)(b << 10) + d) * 32;
            float* o2 = o1 + BDMx;
#pragma unroll
            for (int q = 0; q < 8; q++) {
                float4 v1 = { so[q * 4], so[q * 4 + 1], so[q * 4 + 2], so[q * 4 + 3] };
                float4 v2 = { ao[q * 4], ao[q * 4 + 1], ao[q * 4 + 2], ao[q * 4 + 3] };
                ((float4*)o1)[q] = v1;
                ((float4*)o2)[q] = v2;
            }
            __syncthreads();
        } else {
            float* S = (float*)smem;    // 32*64 floats = 8192B
            int b = vb - 1024;
            bool done = g_dones[b] != 0;
            float* outs = out + 2 * (size_t)BDMx;
            for (int t = tid; t < Mx * NSYx; t += 256) {
                int m = t & 31, j = t >> 5;
                int dd = Dx - NSYx + j;
                float val;
                if (m < 28)
                    val = done ? start_at[dd * 32 + m + 4]
                               : at_in[((size_t)(b * Dx + dd)) * 32 + m + 4];
                else
                    val = g_hat[m - 28][(size_t)dd * Bx + b];
                S[m * NSYx + j] = val;
            }
            __syncthreads();
            for (int s = tid; s < SYNCHx; s += 256) {
                int ti = g_tri_i[s], tj = g_tri_j[s];
                float acc = 0.0f;
#pragma unroll
                for (int m = 0; m < Mx; m++)
                    acc += g_decay[m * SYNCHx + s] * S[m * NSYx + ti] * S[m * NSYx + tj];
                outs[(size_t)b * SYNCHx + s] = acc * g_invden[s];
            }
            __syncthreads();
        }
    }
}

// ================= megakernel: iterations + finalization =================
__global__ void __launch_bounds__(256) k_mega(
    const float* __restrict__ st_in, const float* __restrict__ at_in,
    const float* __restrict__ start_st, const float* __restrict__ start_at,
    const float* __restrict__ syn_b1,
    const float* __restrict__ sln1s, const float* __restrict__ sln1b,
    const float* __restrict__ syn_b2,
    const float* __restrict__ sln2s, const float* __restrict__ sln2b,
    const float* __restrict__ nlm1_b, const float* __restrict__ nlm1_T,
    const float* __restrict__ nlm2_b, const float* __restrict__ nlm2_T,
    float* __restrict__ out)
{
    extern __shared__ char smem_raw[];
    uint32_t sbase = smem_u32(smem_raw);
    uint32_t abase = (sbase + 1023u) & ~1023u;
    char* smem = smem_raw + (abase - sbase);
    unsigned target = 0;

    for (int it = 0; it < ITERSx; it++) {
        // GEMM1: pre(1536) @ ws1^T -> g_y, KS=2 (Kloc=768, NC=12), 256 units
        for (int u = blockIdx.x; u < 256; u += (int)gridDim.x) {
            int col0 = (u & 31) * 64;
            int row0 = ((u >> 5) & 3) * 64;
            int z = u >> 7;
            gemm_unit(g_prehi, g_prelo, g_ws1hi, g_ws1lo,
                      g_y + (size_t)z * Bx * 2048,
                      row0, col0, z * 768, 12, 1536, 1536, 2048, abase);
        }
        gsync(target);
        phase_gluln(syn_b1, sln1s, sln1b, g_h1hi, g_h1lo, nullptr, 0, smem);
        gsync(target);
        // GEMM2: h1(1024) @ ws2^T -> g_y, KS=2 (Kloc=512, NC=8)
        for (int u = blockIdx.x; u < 256; u += (int)gridDim.x) {
            int col0 = (u & 31) * 64;
            int row0 = ((u >> 5) & 3) * 64;
            int z = u >> 7;
            gemm_unit(g_h1hi, g_h1lo, g_ws2hi, g_ws2lo,
                      g_y + (size_t)z * Bx * 2048,
                      row0, col0, z * 512, 8, 1024, 1024, 2048, abase);
        }
        gsync(target);
        phase_gluln(syn_b2, sln2s, sln2b, nullptr, nullptr, &g_hst[it][0], 1, smem);
        gsync(target);
        if (blockIdx.x < 128) {
            switch (it) {
                case 0: nlm_body<0>(st_in, start_st, nlm1_b, nlm1_T, nlm2_b, nlm2_T, smem); break;
                case 1: nlm_body<1>(st_in, start_st, nlm1_b, nlm1_T, nlm2_b, nlm2_T, smem); break;
                case 2: nlm_body<2>(st_in, start_st, nlm1_b, nlm1_T, nlm2_b, nlm2_T, smem); break;
                case 3: nlm_body<3>(st_in, start_st, nlm1_b, nlm1_T, nlm2_b, nlm2_T, smem); break;
            }
        }
        gsync(target);
    }
    phase_fin(out, st_in, at_in, start_st, start_at, smem);
}

// =====================================================================
extern "C" void kernel_launch(void* const* d_in, const int* in_sizes, int n_in,
                              void* d_out, int out_size) {
    (void)in_sizes; (void)n_in; (void)out_size;
    const float* obs      = (const float*)d_in[0];
    const unsigned char* dones_raw = (const unsigned char*)d_in[1];
    const float* st_in    = (const float*)d_in[3];
    const float* at_in    = (const float*)d_in[4];
    const float* start_st = (const float*)d_in[5];
    const float* start_at = (const float*)d_in[6];
    const float* bb_w1    = (const float*)d_in[7];
    const float* bb_b1    = (const float*)d_in[8];
    const float* ln1s     = (const float*)d_in[9];
    const float* ln1b     = (const float*)d_in[10];
    const float* bb_w2    = (const float*)d_in[11];
    const float* bb_b2    = (const float*)d_in[12];
    const float* ln2s     = (const float*)d_in[13];
    const float* ln2b     = (const float*)d_in[14];
    const float* syn_w1   = (const float*)d_in[15];
    const float* syn_b1   = (const float*)d_in[16];
    const float* sln1s    = (const float*)d_in[17];
    const float* sln1b    = (const float*)d_in[18];
    const float* syn_w2   = (const float*)d_in[19];
    const float* syn_b2   = (const float*)d_in[20];
    const float* sln2s    = (const float*)d_in[21];
    const float* sln2b    = (const float*)d_in[22];
    const float* nlm1_w   = (const float*)d_in[23];
    const float* nlm1_b   = (const float*)d_in[24];
    const float* nlm1_T   = (const float*)d_in[25];
    const float* nlm2_w   = (const float*)d_in[26];
    const float* nlm2_b   = (const float*)d_in[27];
    const float* nlm2_T   = (const float*)d_in[28];
    const float* decay_p  = (const float*)d_in[29];
    float* out = (float*)d_out;

    void *p_y, *p_gbar;
    void *p_obshi, *p_obslo, *p_prehi, *p_prelo, *p_h1hi, *p_h1lo;
    void *p_wb1h, *p_wb1l, *p_wb2h, *p_wb2l;
    cudaGetSymbolAddress(&p_y, g_y);
    cudaGetSymbolAddress(&p_gbar, g_gbar);
    cudaGetSymbolAddress(&p_obshi, g_obshi);  cudaGetSymbolAddress(&p_obslo, g_obslo);
    cudaGetSymbolAddress(&p_prehi, g_prehi);  cudaGetSymbolAddress(&p_prelo, g_prelo);
    cudaGetSymbolAddress(&p_h1hi, g_h1hi);    cudaGetSymbolAddress(&p_h1lo, g_h1lo);
    cudaGetSymbolAddress(&p_wb1h, g_wb1hi);   cudaGetSymbolAddress(&p_wb1l, g_wb1lo);
    cudaGetSymbolAddress(&p_wb2h, g_wb2hi);   cudaGetSymbolAddress(&p_wb2l, g_wb2lo);
    float* gy = (float*)p_y;

    static int init_done = 0;
    static cudaStream_t s_side = nullptr;
    static cudaEvent_t ev_fork = nullptr, ev_join = nullptr;
    int gsmem = GSTAGES * GBUF_BYTES + 1024;
    int megasmem = GSTAGES * GBUF_BYTES + 2048;
    if (!init_done) {
        cudaFuncSetAttribute(k_tgemm, cudaFuncAttributeMaxDynamicSharedMemorySize, gsmem);
        cudaFuncSetAttribute(k_mega, cudaFuncAttributeMaxDynamicSharedMemorySize, megasmem);
        cudaStreamCreateWithFlags(&s_side, cudaStreamNonBlocking);
        cudaEventCreateWithFlags(&ev_fork, cudaEventDisableTiming);
        cudaEventCreateWithFlags(&ev_join, cudaEventDisableTiming);
        init_done = 1;
    }

    // fork: side branch preps NLM + synapse weights
    cudaEventRecord(ev_fork, 0);
    cudaStreamWaitEvent(s_side, ev_fork, 0);
    k_prep_side<<<9216, 256, 0, s_side>>>(nlm1_w, nlm2_w, syn_w1, syn_w2);
    cudaEventRecord(ev_join, s_side);

    // main branch: light prep + backbone
    k_prep_main<<<1034, 256>>>(dones_raw, decay_p, obs, bb_w1, bb_w2);

    k_tgemm<<<dim3(16, 4, 2), 256, gsmem>>>(
        (const __nv_bfloat16*)p_obshi, (const __nv_bfloat16*)p_obslo,
        (const __nv_bfloat16*)p_wb1h, (const __nv_bfloat16*)p_wb1l,
        gy, 128, 256, 256, 1024);
    k_gluln_split<<<Bx, 512>>>(gy, 512, 2, bb_b1, ln1s, ln1b,
        (__nv_bfloat16*)p_h1hi, (__nv_bfloat16*)p_h1lo, 512, 0, nullptr, nullptr);
    k_tgemm<<<dim3(16, 4, 2), 256, gsmem>>>(
        (const __nv_bfloat16*)p_h1hi, (const __nv_bfloat16*)p_h1lo,
        (const __nv_bfloat16*)p_wb2h, (const __nv_bfloat16*)p_wb2l,
        gy, 256, 512, 512, 1024);
    k_gluln_split<<<Bx, 512>>>(gy, 512, 2, bb_b2, ln2s, ln2b,
        (__nv_bfloat16*)p_prehi, (__nv_bfloat16*)p_prelo, 1536, 1, at_in, start_at);

    // join + reset barrier counter, then one persistent kernel for the rest
    cudaStreamWaitEvent(0, ev_join, 0);
    cudaMemsetAsync(p_gbar, 0, sizeof(unsigned), 0);
    k_mega<<<NBLK, 256, megasmem>>>(
        st_in, at_in, start_st, start_at,
        syn_b1, sln1s, sln1b, syn_b2, sln2s, sln2b,
        nlm1_b, nlm1_T, nlm2_b, nlm2_T, out);
}